// round 15
// baseline (speedup 1.0000x reference)
#include <cuda_runtime.h>
#include <cuda_fp16.h>
#include <cstdint>

#define B_SIZE 131072
#define NAG 8
#define HXS 64
#define ENC 128
#define ACTS 5
#define TILE 128
#define NBLK (B_SIZE / TILE)   // 1024
#define NREP 64                // g_comm replicas (atomic-contention spread)

// scratch (device globals: no allocation allowed)
__device__ float g_commR[NREP][NAG * HXS];   // replicated accumulators, 128 KB
__device__ float g_pre2[NAG * HXS];
// packed fp16 z (= h @ Wc_low, pre-bias) in per-thread fragment order:
// per CTA 1024 uint4 (jp=0..3; index jp*256+tid)
__device__ uint4 g_hpk[(size_t)NBLK * NAG * 1024];   // 128 MiB

// ---------------------------------------------------------------------------
// helpers
// ---------------------------------------------------------------------------
__device__ __forceinline__ uint32_t pack_f16x2(float lo, float hi) {
    // lo -> lower 16 bits, hi -> upper 16 bits
    uint32_t r;
    asm("cvt.rn.f16x2.f32 %0, %1, %2;" : "=r"(r) : "f"(hi), "f"(lo));
    return r;
}
__device__ __forceinline__ uint32_t split_pack_f16(float v0, float v1, uint32_t &lop) {
    uint32_t hp = pack_f16x2(v0, v1);
    float f0 = __half2float(__ushort_as_half((unsigned short)(hp & 0xffffu)));
    float f1 = __half2float(__ushort_as_half((unsigned short)(hp >> 16)));
    lop = pack_f16x2(v0 - f0, v1 - f1);
    return hp;
}
__device__ __forceinline__ void mma_f16(float* d, uint32_t a0, uint32_t a1,
                                        uint32_t a2, uint32_t a3,
                                        uint32_t b0, uint32_t b1) {
    asm volatile(
        "mma.sync.aligned.m16n8k16.row.col.f32.f16.f16.f32 "
        "{%0,%1,%2,%3}, {%4,%5,%6,%7}, {%8,%9}, {%0,%1,%2,%3};"
        : "+f"(d[0]), "+f"(d[1]), "+f"(d[2]), "+f"(d[3])
        : "r"(a0), "r"(a1), "r"(a2), "r"(a3), "r"(b0), "r"(b1));
}
__device__ __forceinline__ void ldm_x4(uint32_t &r0, uint32_t &r1, uint32_t &r2,
                                       uint32_t &r3, uint32_t addr) {
    asm volatile("ldmatrix.sync.aligned.m8n8.x4.shared.b16 {%0,%1,%2,%3}, [%4];"
                 : "=r"(r0), "=r"(r1), "=r"(r2), "=r"(r3) : "r"(addr));
}
__device__ __forceinline__ void ldm_x4_t(uint32_t &r0, uint32_t &r1, uint32_t &r2,
                                         uint32_t &r3, uint32_t addr) {
    asm volatile("ldmatrix.sync.aligned.m8n8.x4.trans.shared.b16 {%0,%1,%2,%3}, [%4];"
                 : "=r"(r0), "=r"(r1), "=r"(r2), "=r"(r3) : "r"(addr));
}
__device__ __forceinline__ float fast_tanh(float x) {
    float r; asm("tanh.approx.f32 %0, %1;" : "=f"(r) : "f"(x)); return r;
}

__global__ void k_zero() {
    g_commR[blockIdx.x][threadIdx.x] = 0.f;
}

// ---------------------------------------------------------------------------
// Kernel A layout (floats):
//   obs 2048 | W1 256 | b1 128 | b2 64 | BIG 9216 | sC 1056 = 12768 (51,072 B)
// BIG phases:
//   encoder:      WTH u32[64][68] @ +0, WTL @ +4352
//   post-encoder: CTH u32[64][36] @ +0, CTL @ +2304, sHp u32[128][36] @ +4608
//   final:        partials f32[8][520] @ +0
// ---------------------------------------------------------------------------
#define C_OBS 0
#define C_W1  2048
#define C_B1  2304
#define C_B2  2432
#define C_BIG 2496
#define C_SC  11712
#define C_TOT 12768

__device__ __forceinline__ void stage_common(
    float* sObs, float* sW1, float* sb1, float* sb2,
    uint32_t* sWTH, uint32_t* sWTL,
    int n, int tid, int b0,
    const float* __restrict__ obs, const float* __restrict__ W1,
    const float* __restrict__ b1, const float* __restrict__ W2,
    const float* __restrict__ b2)
{
    {
        const float4* src = (const float4*)(obs + (size_t)b0 * 16);
        float4* dst = (float4*)sObs;
        dst[tid]       = src[tid];
        dst[tid + 256] = src[tid + 256];
    }
    sW1[tid] = W1[n * 256 + tid];
    if (tid < 128) sb1[tid] = b1[n * 128 + tid];
    if (tid < 64)  sb2[tid] = b2[n * 64 + tid];
    // W2 [128][64] -> packed k-pairs, transposed fp16 hi/lo planes [64 o][68]
    for (int i = tid; i < 64 * 64; i += 256) {
        int k2 = i >> 6, o = i & 63;
        float v0 = W2[n * ENC * HXS + (2 * k2) * 64 + o];
        float v1 = W2[n * ENC * HXS + (2 * k2 + 1) * 64 + o];
        uint32_t lo, hi = split_pack_f16(v0, v1, lo);
        sWTH[o * 68 + k2] = hi;
        sWTL[o * 68 + k2] = lo;
    }
}

// encoder MMA: fp16 activations x (fp16 hi+lo weights), on-the-fly h1 A-frags
__device__ __forceinline__ void encoder_mma(
    const float* sObs, const float* sW1, const float* sb1,
    const uint32_t* sWTH, const uint32_t* sWTL,
    int n, int tid, float acc[8][4])
{
    const int w = tid >> 5, lane = tid & 31, g = lane >> 2, t = lane & 3;
    const int r0 = w * 16 + g, r1 = r0 + 8;
    const int mm = lane >> 3, rr = lane & 7;
    const float o00 = sObs[r0 * 16 + 2 * n], o01 = sObs[r0 * 16 + 2 * n + 1];
    const float o10 = sObs[r1 * 16 + 2 * n], o11 = sObs[r1 * 16 + 2 * n + 1];

    const uint32_t wbH = (uint32_t)__cvta_generic_to_shared(sWTH) +
                         (((mm >> 1) * 8 + rr) * 68 + (mm & 1) * 4) * 4;
    const uint32_t wbL = (uint32_t)__cvta_generic_to_shared(sWTL) +
                         (((mm >> 1) * 8 + rr) * 68 + (mm & 1) * 4) * 4;

#pragma unroll
    for (int nt = 0; nt < 8; nt++)
#pragma unroll
        for (int e = 0; e < 4; e++) acc[nt][e] = 0.f;

#pragma unroll
    for (int kk = 0; kk < 8; kk++) {
        const int c0 = kk * 16 + 2 * t;
        const int c8 = c0 + 8;
        float wA0 = sW1[c0],     wB0 = sW1[128 + c0],     bb0 = sb1[c0];
        float wA1 = sW1[c0 + 1], wB1 = sW1[128 + c0 + 1], bb1 = sb1[c0 + 1];
        float wA8 = sW1[c8],     wB8 = sW1[128 + c8],     bb8 = sb1[c8];
        float wA9 = sW1[c8 + 1], wB9 = sW1[128 + c8 + 1], bb9 = sb1[c8 + 1];

        float v00 = fmaxf(fmaf(o00, wA0, fmaf(o01, wB0, bb0)), 0.f);
        float v01 = fmaxf(fmaf(o00, wA1, fmaf(o01, wB1, bb1)), 0.f);
        float v10 = fmaxf(fmaf(o10, wA0, fmaf(o11, wB0, bb0)), 0.f);
        float v11 = fmaxf(fmaf(o10, wA1, fmaf(o11, wB1, bb1)), 0.f);
        float v08 = fmaxf(fmaf(o00, wA8, fmaf(o01, wB8, bb8)), 0.f);
        float v09 = fmaxf(fmaf(o00, wA9, fmaf(o01, wB9, bb9)), 0.f);
        float v18 = fmaxf(fmaf(o10, wA8, fmaf(o11, wB8, bb8)), 0.f);
        float v19 = fmaxf(fmaf(o10, wA9, fmaf(o11, wB9, bb9)), 0.f);

        uint32_t a0 = pack_f16x2(v00, v01);
        uint32_t a1 = pack_f16x2(v10, v11);
        uint32_t a2 = pack_f16x2(v08, v09);
        uint32_t a3 = pack_f16x2(v18, v19);

        const uint32_t kof = kk * 32;
#pragma unroll
        for (int jp = 0; jp < 4; jp++) {
            uint32_t bh0a, bh1a, bh0b, bh1b, bl0a, bl1a, bl0b, bl1b;
            ldm_x4(bh0a, bh1a, bh0b, bh1b, wbH + jp * 4352 + kof);
            ldm_x4(bl0a, bl1a, bl0b, bl1b, wbL + jp * 4352 + kof);
            mma_f16(acc[2 * jp],     a0, a1, a2, a3, bh0a, bh1a);
            mma_f16(acc[2 * jp],     a0, a1, a2, a3, bl0a, bl1a);
            mma_f16(acc[2 * jp + 1], a0, a1, a2, a3, bh0b, bh1b);
            mma_f16(acc[2 * jp + 1], a0, a1, a2, a3, bl0b, bl1b);
        }
    }
}

__global__ __launch_bounds__(256, 4) void k_comm(
    const float* __restrict__ obs, const float* __restrict__ W1,
    const float* __restrict__ b1, const float* __restrict__ W2,
    const float* __restrict__ b2, const float* __restrict__ Wc)
{
    extern __shared__ float sm[];
    float* sObs = sm + C_OBS;
    float* sW1  = sm + C_W1;
    float* sb1  = sm + C_B1;
    float* sb2  = sm + C_B2;
    uint32_t* BIGu = (uint32_t*)(sm + C_BIG);
    float* sC = sm + C_SC;                    // [8][132]

    const int n   = blockIdx.y;
    const int tid = threadIdx.x;
    const int b0  = blockIdx.x * TILE;

    stage_common(sObs, sW1, sb1, sb2, BIGu, BIGu + 4352, n, tid, b0,
                 obs, W1, b1, W2, b2);
    __syncthreads();

    float acc[8][4];
    encoder_mma(sObs, sW1, sb1, BIGu, BIGu + 4352, n, tid, acc);
    __syncthreads();   // encoder weight planes dead; BIG repurposed below

    uint32_t* sCTH = BIGu;          // Wc_low hi, [64 o][36]
    uint32_t* sCTL = BIGu + 2304;   // Wc_low lo
    uint32_t* sHp  = BIGu + 4608;   // fp16 H tile [128 bb][36], 144B rows

    const int w = tid >> 5, lane = tid & 31, g = lane >> 2, t = lane & 3;
    const int r0 = w * 16 + g, r1 = r0 + 8;
    const int mm = lane >> 3, rr = lane & 7;

    // stage Wc_low planes (reads same 16KB per agent -> L2-hot)
    for (int i = tid; i < 32 * 64; i += 256) {
        int k2 = i >> 6, o = i & 63;
        float v0 = Wc[n * 2 * HXS * HXS + (2 * k2) * 64 + o];
        float v1 = Wc[n * 2 * HXS * HXS + (2 * k2 + 1) * 64 + o];
        uint32_t lo, hi = split_pack_f16(v0, v1, lo);
        sCTH[o * 36 + k2] = hi;
        sCTL[o * 36 + k2] = lo;
    }

    // epilogue: h = relu(acc + b2) -> fp16 packed straight into sHp
#pragma unroll
    for (int nt = 0; nt < 8; nt++) {
        int c0 = nt * 8 + 2 * t;
        float p0 = sb2[c0], p1 = sb2[c0 + 1];
        float v00 = fmaxf(acc[nt][0] + p0, 0.f);
        float v01 = fmaxf(acc[nt][1] + p1, 0.f);
        float v10 = fmaxf(acc[nt][2] + p0, 0.f);
        float v11 = fmaxf(acc[nt][3] + p1, 0.f);
        sHp[r0 * 36 + nt * 4 + t] = pack_f16x2(v00, v01);
        sHp[r1 * 36 + nt * 4 + t] = pack_f16x2(v10, v11);
    }

    // comm coefficients: coef_i = mask[i][n] / J[i]
    if (tid < 128) {
        float px[NAG], py[NAG];
#pragma unroll
        for (int j = 0; j < NAG; j++) {
            px[j] = sObs[tid * 16 + 2 * j] * 2.0f;       // GRID[0]-1
            py[j] = sObs[tid * 16 + 2 * j + 1] * 6.0f;   // GRID[1]-1
        }
#pragma unroll
        for (int i = 0; i < NAG; i++) {
            float J = 0.f, mn = 0.f;
#pragma unroll
            for (int j = 0; j < NAG; j++) {
                float d = fabsf(px[i] - px[j]) + fabsf(py[i] - py[j]);
                bool msk = (d > 0.f) && (d < 2.0f);
                J += msk ? 1.f : 0.f;
                if (j == n) mn = msk ? 1.f : 0.f;
            }
            if (J <= 0.f) J = 1.f;
            sC[i * 132 + tid] = mn / J;
        }
    }
    __syncthreads();

    // ---- decoder GEMM, jp-outer: z = h @ Wc_low (A re-loaded via ldmatrix)
    {
        const uint32_t abase = (uint32_t)__cvta_generic_to_shared(sHp) +
                               ((w * 16 + (mm & 1) * 8 + rr) * 36 + (mm >> 1) * 4) * 4;
        const uint32_t cbH = (uint32_t)__cvta_generic_to_shared(sCTH) +
                             (((mm >> 1) * 8 + rr) * 36 + (mm & 1) * 4) * 4;
        const uint32_t cbL = (uint32_t)__cvta_generic_to_shared(sCTL) +
                             (((mm >> 1) * 8 + rr) * 36 + (mm & 1) * 4) * 4;
        const int ctaL = blockIdx.y * gridDim.x + blockIdx.x;
        uint4* gp = g_hpk + (size_t)ctaL * 1024;

#pragma unroll
        for (int jp = 0; jp < 4; jp++) {
            float az0[4] = {0.f, 0.f, 0.f, 0.f};
            float az1[4] = {0.f, 0.f, 0.f, 0.f};
#pragma unroll
            for (int kk = 0; kk < 4; kk++) {
                uint32_t a0, a1, a2, a3;
                ldm_x4(a0, a1, a2, a3, abase + kk * 32);
                uint32_t bh0a, bh1a, bh0b, bh1b, bl0a, bl1a, bl0b, bl1b;
                ldm_x4(bh0a, bh1a, bh0b, bh1b, cbH + jp * 2304 + kk * 32);
                ldm_x4(bl0a, bl1a, bl0b, bl1b, cbL + jp * 2304 + kk * 32);
                mma_f16(az0, a0, a1, a2, a3, bh0a, bh1a);
                mma_f16(az0, a0, a1, a2, a3, bl0a, bl1a);
                mma_f16(az1, a0, a1, a2, a3, bh0b, bh1b);
                mma_f16(az1, a0, a1, a2, a3, bl0b, bl1b);
            }
            uint4 Z;
            Z.x = pack_f16x2(az0[0], az0[1]);   // nt=2jp,   row r0
            Z.y = pack_f16x2(az0[2], az0[3]);   // nt=2jp,   row r1
            Z.z = pack_f16x2(az1[0], az1[1]);   // nt=2jp+1, row r0
            Z.w = pack_f16x2(az1[2], az1[3]);   // nt=2jp+1, row r1
            gp[jp * 256 + tid] = Z;
        }
    }

    // ---- MMA comm reduction: warp w contracts its own bb chunk [16w,16w+16)
    float dv[4][4];   // [jp][dA0,dA1,dB0,dB1]
    {
        uint32_t hb = (uint32_t)__cvta_generic_to_shared(sHp) +
                      (w * 16 + (mm & 1) * 8 + rr) * 144 + (mm >> 1) * 16;
        float2 cA = *(const float2*)(sC + g * 132 + 16 * w + 2 * t);
        float2 cB = *(const float2*)(sC + g * 132 + 16 * w + 8 + 2 * t);
        uint32_t a0l, a0h = split_pack_f16(cA.x, cA.y, a0l);
        uint32_t a2l, a2h = split_pack_f16(cB.x, cB.y, a2l);
#pragma unroll
        for (int jp = 0; jp < 4; jp++) {
            uint32_t b0a, b1a, b0b, b1b;
            ldm_x4_t(b0a, b1a, b0b, b1b, hb + jp * 32);
            float dA[4] = {0.f, 0.f, 0.f, 0.f};
            float dB[4] = {0.f, 0.f, 0.f, 0.f};
            mma_f16(dA, a0h, 0u, a2h, 0u, b0a, b1a);
            mma_f16(dA, a0l, 0u, a2l, 0u, b0a, b1a);
            mma_f16(dB, a0h, 0u, a2h, 0u, b0b, b1b);
            mma_f16(dB, a0l, 0u, a2l, 0u, b0b, b1b);
            dv[jp][0] = dA[0]; dv[jp][1] = dA[1];
            dv[jp][2] = dB[0]; dv[jp][3] = dB[1];
        }
    }
    __syncthreads();   // all reads of BIG (Wc planes + sHp) complete

    // stage per-warp partials into the dead BIG region: [w][i*65 + o]
    {
        float* sPart = sm + C_BIG;
#pragma unroll
        for (int jp = 0; jp < 4; jp++) {
            int oA = 16 * jp + 2 * t, oB = oA + 8;
            sPart[w * 520 + g * 65 + oA]     = dv[jp][0];
            sPart[w * 520 + g * 65 + oA + 1] = dv[jp][1];
            sPart[w * 520 + g * 65 + oB]     = dv[jp][2];
            sPart[w * 520 + g * 65 + oB + 1] = dv[jp][3];
        }
    }
    __syncthreads();

    // cross-warp sum: 512 outputs over 256 threads; one atomic each into a
    // REPLICATED accumulator (spreads L2 same-address atomic contention 64x)
    {
        const float* sPart = sm + C_BIG;
        float* rep = g_commR[blockIdx.x & (NREP - 1)];
#pragma unroll
        for (int s = 0; s < 2; s++) {
            int idx = tid + s * 256;
            int i = idx >> 6, o = idx & 63;
            float sum = 0.f;
#pragma unroll
            for (int ww = 0; ww < 8; ww++)
                sum += sPart[ww * 520 + i * 65 + o];
            atomicAdd(&rep[idx], sum);
        }
    }
}

// pre2[n][o] = bc[n][o] + sum_h comm[n][h] * Wc[n][HX+h][o]
// comm[n][h] = sum over the 64 replicas
__global__ void k_pre(const float* __restrict__ Wc, const float* __restrict__ bc) {
    __shared__ float sComm[HXS];
    const int n = blockIdx.x, o = threadIdx.x;
    float cs = 0.f;
#pragma unroll 8
    for (int r = 0; r < NREP; r++)
        cs += g_commR[r][n * HXS + o];
    sComm[o] = cs;
    __syncthreads();
    float s = bc[n * HXS + o];
#pragma unroll 8
    for (int h = 0; h < HXS; h++)
        s = fmaf(sComm[h], Wc[n * 2 * HXS * HXS + (HXS + h) * HXS + o], s);
    g_pre2[n * HXS + o] = s;
}

// ---------------------------------------------------------------------------
// Kernel B: pure streaming epilogue — q = tanh(z + pre2) @ Wd + bd.
// ---------------------------------------------------------------------------
__global__ __launch_bounds__(256) void k_main(
    const float* __restrict__ Wd, const float* __restrict__ bd,
    float* __restrict__ out)
{
    __shared__ float sWd[HXS * ACTS];
    __shared__ float sP[HXS];
    __shared__ float sbd[8];

    const int tid = threadIdx.x;
    const int ctaL = NBLK * NAG - 1 - (blockIdx.y * gridDim.x + blockIdx.x);
    const int n    = ctaL / NBLK;
    const int b0   = (ctaL % NBLK) * TILE;

    for (int i = tid; i < HXS * ACTS; i += 256) sWd[i] = Wd[n * HXS * ACTS + i];
    if (tid < 64) sP[tid] = g_pre2[n * 64 + tid];
    if (tid < 5)  sbd[tid] = bd[n * 5 + tid];
    __syncthreads();

    const int lane = tid & 31, g = lane >> 2, t = lane & 3, w = tid >> 5;
    const int r0 = w * 16 + g, r1 = r0 + 8;
    const uint4* gp = g_hpk + (size_t)ctaL * 1024;

    float q0[ACTS], q1[ACTS];
#pragma unroll
    for (int a = 0; a < ACTS; a++) { q0[a] = 0.f; q1[a] = 0.f; }

#pragma unroll
    for (int jp = 0; jp < 4; jp++) {
        uint4 Z = gp[jp * 256 + tid];
#pragma unroll
        for (int s = 0; s < 2; s++) {
            int nt = 2 * jp + s;
            int c0 = nt * 8 + 2 * t;
            float p0 = sP[c0], p1 = sP[c0 + 1];
            uint32_t zr0 = s ? Z.z : Z.x;   // row r0: (c0, c0+1)
            uint32_t zr1 = s ? Z.w : Z.y;   // row r1
            float2 fa = __half22float2(*(const __half2*)&zr0);
            float2 fb = __half22float2(*(const __half2*)&zr1);
            float t00 = fast_tanh(fa.x + p0);
            float t01 = fast_tanh(fa.y + p1);
            float t10 = fast_tanh(fb.x + p0);
            float t11 = fast_tanh(fb.y + p1);
            const float* wd0 = sWd + c0 * 5;
            const float* wd1 = sWd + (c0 + 1) * 5;
#pragma unroll
            for (int a = 0; a < ACTS; a++) {
                q0[a] = fmaf(t00, wd0[a], fmaf(t01, wd1[a], q0[a]));
                q1[a] = fmaf(t10, wd0[a], fmaf(t11, wd1[a], q1[a]));
            }
        }
    }
#pragma unroll
    for (int a = 0; a < ACTS; a++) {
        q0[a] += __shfl_xor_sync(0xffffffffu, q0[a], 1);
        q0[a] += __shfl_xor_sync(0xffffffffu, q0[a], 2);
        q1[a] += __shfl_xor_sync(0xffffffffu, q1[a], 1);
        q1[a] += __shfl_xor_sync(0xffffffffu, q1[a], 2);
    }
    if (t == 0) {
        float* o0 = out + ((size_t)(b0 + r0) * NAG + n) * ACTS;
        float* o1 = out + ((size_t)(b0 + r1) * NAG + n) * ACTS;
#pragma unroll
        for (int a = 0; a < ACTS; a++) {
            o0[a] = q0[a] + sbd[a];
            o1[a] = q1[a] + sbd[a];
        }
    }
}

extern "C" void kernel_launch(void* const* d_in, const int* in_sizes, int n_in,
                              void* d_out, int out_size)
{
    const float* obs = (const float*)d_in[0];
    const float* W1  = (const float*)d_in[1];
    const float* b1  = (const float*)d_in[2];
    const float* W2  = (const float*)d_in[3];
    const float* b2  = (const float*)d_in[4];
    const float* Wc  = (const float*)d_in[5];
    const float* bc  = (const float*)d_in[6];
    const float* Wd  = (const float*)d_in[7];
    const float* bd  = (const float*)d_in[8];
    float* out = (float*)d_out;

    const int SMEM_C = C_TOT * sizeof(float);   // 51,072 B -> 4 CTAs/SM
    cudaFuncSetAttribute(k_comm, cudaFuncAttributeMaxDynamicSharedMemorySize, SMEM_C);

    k_zero<<<NREP, NAG * HXS>>>();
    k_comm<<<dim3(NBLK, NAG), 256, SMEM_C>>>(obs, W1, b1, W2, b2, Wc);
    k_pre<<<NAG, HXS>>>(Wc, bc);
    k_main<<<dim3(NBLK, NAG), 256>>>(Wd, bd, out);
}

// round 17
// speedup vs baseline: 1.0617x; 1.0617x over previous
#include <cuda_runtime.h>
#include <cuda_fp16.h>
#include <cstdint>

#define B_SIZE 131072
#define NAG 8
#define HXS 64
#define ENC 128
#define ACTS 5
#define TILE 128
#define NBLK (B_SIZE / TILE)   // 1024
#define NREP 64                // g_comm replicas

// scratch (device globals: no allocation allowed)
__device__ float g_commR[NREP][NAG * HXS];
__device__ float g_pre2[NAG * HXS];
// packed fp16 z (= h @ Wc_low, pre-bias) in per-thread fragment order:
// per CTA 1024 uint4 (jp=0..3; index jp*256+tid)
__device__ uint4 g_hpk[(size_t)NBLK * NAG * 1024];   // 128 MiB

// ---------------------------------------------------------------------------
// helpers
// ---------------------------------------------------------------------------
__device__ __forceinline__ uint32_t pack_f16x2(float lo, float hi) {
    uint32_t r;
    asm("cvt.rn.f16x2.f32 %0, %1, %2;" : "=r"(r) : "f"(hi), "f"(lo));
    return r;
}
__device__ __forceinline__ uint32_t split_pack_f16(float v0, float v1, uint32_t &lop) {
    uint32_t hp = pack_f16x2(v0, v1);
    float f0 = __half2float(__ushort_as_half((unsigned short)(hp & 0xffffu)));
    float f1 = __half2float(__ushort_as_half((unsigned short)(hp >> 16)));
    lop = pack_f16x2(v0 - f0, v1 - f1);
    return hp;
}
__device__ __forceinline__ void mma_f16(float* d, uint32_t a0, uint32_t a1,
                                        uint32_t a2, uint32_t a3,
                                        uint32_t b0, uint32_t b1) {
    asm volatile(
        "mma.sync.aligned.m16n8k16.row.col.f32.f16.f16.f32 "
        "{%0,%1,%2,%3}, {%4,%5,%6,%7}, {%8,%9}, {%0,%1,%2,%3};"
        : "+f"(d[0]), "+f"(d[1]), "+f"(d[2]), "+f"(d[3])
        : "r"(a0), "r"(a1), "r"(a2), "r"(a3), "r"(b0), "r"(b1));
}
__device__ __forceinline__ void ldm_x4(uint32_t &r0, uint32_t &r1, uint32_t &r2,
                                       uint32_t &r3, uint32_t addr) {
    asm volatile("ldmatrix.sync.aligned.m8n8.x4.shared.b16 {%0,%1,%2,%3}, [%4];"
                 : "=r"(r0), "=r"(r1), "=r"(r2), "=r"(r3) : "r"(addr));
}
__device__ __forceinline__ void ldm_x4_t(uint32_t &r0, uint32_t &r1, uint32_t &r2,
                                         uint32_t &r3, uint32_t addr) {
    asm volatile("ldmatrix.sync.aligned.m8n8.x4.trans.shared.b16 {%0,%1,%2,%3}, [%4];"
                 : "=r"(r0), "=r"(r1), "=r"(r2), "=r"(r3) : "r"(addr));
}
__device__ __forceinline__ float fast_tanh(float x) {
    float r; asm("tanh.approx.f32 %0, %1;" : "=f"(r) : "f"(x)); return r;
}

__global__ void k_zero() {
    g_commR[blockIdx.x][threadIdx.x] = 0.f;
}

// ---------------------------------------------------------------------------
// Kernel A layout (floats):
//   obs 2048 | W1 256 | b1 128 | b2 64 | BIG 8704 | sC 1056 = 12256 (49,024 B)
// BIG phases:
//   encoder:      WTH u32[64][68] @ +0, WTL @ +4352  (W2 hi/lo — comm needs
//                 the systematic part of h accurate)
//   post-encoder: CT u32[64][36] @ +0 (fp16 Wc_low single plane),
//                 sHp u32[128][36] @ +2304
//   final:        partials f32[8][520] @ +0
// ---------------------------------------------------------------------------
#define C_OBS 0
#define C_W1  2048
#define C_B1  2304
#define C_B2  2432
#define C_BIG 2496
#define C_SC  11200
#define C_TOT 12256

__device__ __forceinline__ void stage_common(
    float* sObs, float* sW1, float* sb1, float* sb2,
    uint32_t* sWTH, uint32_t* sWTL,
    int n, int tid, int b0,
    const float* __restrict__ obs, const float* __restrict__ W1,
    const float* __restrict__ b1, const float* __restrict__ W2,
    const float* __restrict__ b2)
{
    {
        const float4* src = (const float4*)(obs + (size_t)b0 * 16);
        float4* dst = (float4*)sObs;
        dst[tid]       = src[tid];
        dst[tid + 256] = src[tid + 256];
    }
    sW1[tid] = W1[n * 256 + tid];
    if (tid < 128) sb1[tid] = b1[n * 128 + tid];
    if (tid < 64)  sb2[tid] = b2[n * 64 + tid];
    // W2 [128][64] -> packed k-pairs, transposed fp16 hi/lo planes [64 o][68]
    for (int i = tid; i < 64 * 64; i += 256) {
        int k2 = i >> 6, o = i & 63;
        float v0 = W2[n * ENC * HXS + (2 * k2) * 64 + o];
        float v1 = W2[n * ENC * HXS + (2 * k2 + 1) * 64 + o];
        uint32_t lo, hi = split_pack_f16(v0, v1, lo);
        sWTH[o * 68 + k2] = hi;
        sWTL[o * 68 + k2] = lo;
    }
}

// encoder MMA: fp16 A (on-the-fly h1) x fp16 hi+lo W2
__device__ __forceinline__ void encoder_mma(
    const float* sObs, const float* sW1, const float* sb1,
    const uint32_t* sWTH, const uint32_t* sWTL,
    int n, int tid, float acc[8][4])
{
    const int w = tid >> 5, lane = tid & 31, g = lane >> 2, t = lane & 3;
    const int r0 = w * 16 + g, r1 = r0 + 8;
    const int mm = lane >> 3, rr = lane & 7;
    const float o00 = sObs[r0 * 16 + 2 * n], o01 = sObs[r0 * 16 + 2 * n + 1];
    const float o10 = sObs[r1 * 16 + 2 * n], o11 = sObs[r1 * 16 + 2 * n + 1];

    const uint32_t wbH = (uint32_t)__cvta_generic_to_shared(sWTH) +
                         (((mm >> 1) * 8 + rr) * 68 + (mm & 1) * 4) * 4;
    const uint32_t wbL = (uint32_t)__cvta_generic_to_shared(sWTL) +
                         (((mm >> 1) * 8 + rr) * 68 + (mm & 1) * 4) * 4;

#pragma unroll
    for (int nt = 0; nt < 8; nt++)
#pragma unroll
        for (int e = 0; e < 4; e++) acc[nt][e] = 0.f;

#pragma unroll
    for (int kk = 0; kk < 8; kk++) {
        const int c0 = kk * 16 + 2 * t;
        const int c8 = c0 + 8;
        float wA0 = sW1[c0],     wB0 = sW1[128 + c0],     bb0 = sb1[c0];
        float wA1 = sW1[c0 + 1], wB1 = sW1[128 + c0 + 1], bb1 = sb1[c0 + 1];
        float wA8 = sW1[c8],     wB8 = sW1[128 + c8],     bb8 = sb1[c8];
        float wA9 = sW1[c8 + 1], wB9 = sW1[128 + c8 + 1], bb9 = sb1[c8 + 1];

        float v00 = fmaxf(fmaf(o00, wA0, fmaf(o01, wB0, bb0)), 0.f);
        float v01 = fmaxf(fmaf(o00, wA1, fmaf(o01, wB1, bb1)), 0.f);
        float v10 = fmaxf(fmaf(o10, wA0, fmaf(o11, wB0, bb0)), 0.f);
        float v11 = fmaxf(fmaf(o10, wA1, fmaf(o11, wB1, bb1)), 0.f);
        float v08 = fmaxf(fmaf(o00, wA8, fmaf(o01, wB8, bb8)), 0.f);
        float v09 = fmaxf(fmaf(o00, wA9, fmaf(o01, wB9, bb9)), 0.f);
        float v18 = fmaxf(fmaf(o10, wA8, fmaf(o11, wB8, bb8)), 0.f);
        float v19 = fmaxf(fmaf(o10, wA9, fmaf(o11, wB9, bb9)), 0.f);

        uint32_t a0 = pack_f16x2(v00, v01);
        uint32_t a1 = pack_f16x2(v10, v11);
        uint32_t a2 = pack_f16x2(v08, v09);
        uint32_t a3 = pack_f16x2(v18, v19);

        const uint32_t kof = kk * 32;
#pragma unroll
        for (int jp = 0; jp < 4; jp++) {
            uint32_t bh0a, bh1a, bh0b, bh1b, bl0a, bl1a, bl0b, bl1b;
            ldm_x4(bh0a, bh1a, bh0b, bh1b, wbH + jp * 4352 + kof);
            ldm_x4(bl0a, bl1a, bl0b, bl1b, wbL + jp * 4352 + kof);
            mma_f16(acc[2 * jp],     a0, a1, a2, a3, bh0a, bh1a);
            mma_f16(acc[2 * jp],     a0, a1, a2, a3, bl0a, bl1a);
            mma_f16(acc[2 * jp + 1], a0, a1, a2, a3, bh0b, bh1b);
            mma_f16(acc[2 * jp + 1], a0, a1, a2, a3, bl0b, bl1b);
        }
    }
}

__global__ __launch_bounds__(256, 4) void k_comm(
    const float* __restrict__ obs, const float* __restrict__ W1,
    const float* __restrict__ b1, const float* __restrict__ W2,
    const float* __restrict__ b2, const float* __restrict__ Wc)
{
    extern __shared__ float sm[];
    float* sObs = sm + C_OBS;
    float* sW1  = sm + C_W1;
    float* sb1  = sm + C_B1;
    float* sb2  = sm + C_B2;
    uint32_t* BIGu = (uint32_t*)(sm + C_BIG);
    float* sC = sm + C_SC;                    // [8][132]

    const int n   = blockIdx.y;
    const int tid = threadIdx.x;
    const int b0  = blockIdx.x * TILE;

    stage_common(sObs, sW1, sb1, sb2, BIGu, BIGu + 4352, n, tid, b0,
                 obs, W1, b1, W2, b2);
    __syncthreads();

    float acc[8][4];
    encoder_mma(sObs, sW1, sb1, BIGu, BIGu + 4352, n, tid, acc);
    __syncthreads();   // encoder weight planes dead; BIG repurposed below

    uint32_t* sCT = BIGu;          // Wc_low fp16 single plane, [64 o][36]
    uint32_t* sHp = BIGu + 2304;   // fp16 H tile [128 bb][36], 144B rows

    const int w = tid >> 5, lane = tid & 31, g = lane >> 2, t = lane & 3;
    const int r0 = w * 16 + g, r1 = r0 + 8;
    const int mm = lane >> 3, rr = lane & 7;

    // stage Wc_low plane (fp16 single — z path is saturation-suppressed)
    for (int i = tid; i < 32 * 64; i += 256) {
        int k2 = i >> 6, o = i & 63;
        float v0 = Wc[n * 2 * HXS * HXS + (2 * k2) * 64 + o];
        float v1 = Wc[n * 2 * HXS * HXS + (2 * k2 + 1) * 64 + o];
        sCT[o * 36 + k2] = pack_f16x2(v0, v1);
    }

    // epilogue: h = relu(acc + b2) -> fp16 packed straight into sHp
#pragma unroll
    for (int nt = 0; nt < 8; nt++) {
        int c0 = nt * 8 + 2 * t;
        float p0 = sb2[c0], p1 = sb2[c0 + 1];
        float v00 = fmaxf(acc[nt][0] + p0, 0.f);
        float v01 = fmaxf(acc[nt][1] + p1, 0.f);
        float v10 = fmaxf(acc[nt][2] + p0, 0.f);
        float v11 = fmaxf(acc[nt][3] + p1, 0.f);
        sHp[r0 * 36 + nt * 4 + t] = pack_f16x2(v00, v01);
        sHp[r1 * 36 + nt * 4 + t] = pack_f16x2(v10, v11);
    }

    // comm coefficients: coef_i = mask[i][n] / J[i]
    if (tid < 128) {
        float px[NAG], py[NAG];
#pragma unroll
        for (int j = 0; j < NAG; j++) {
            px[j] = sObs[tid * 16 + 2 * j] * 2.0f;       // GRID[0]-1
            py[j] = sObs[tid * 16 + 2 * j + 1] * 6.0f;   // GRID[1]-1
        }
#pragma unroll
        for (int i = 0; i < NAG; i++) {
            float J = 0.f, mn = 0.f;
#pragma unroll
            for (int j = 0; j < NAG; j++) {
                float d = fabsf(px[i] - px[j]) + fabsf(py[i] - py[j]);
                bool msk = (d > 0.f) && (d < 2.0f);
                J += msk ? 1.f : 0.f;
                if (j == n) mn = msk ? 1.f : 0.f;
            }
            if (J <= 0.f) J = 1.f;
            sC[i * 132 + tid] = mn / J;
        }
    }
    __syncthreads();

    // ---- decoder GEMM, jp-outer: z = h @ Wc_low (single fp16 plane) ----
    {
        const uint32_t abase = (uint32_t)__cvta_generic_to_shared(sHp) +
                               ((w * 16 + (mm & 1) * 8 + rr) * 36 + (mm >> 1) * 4) * 4;
        const uint32_t cb = (uint32_t)__cvta_generic_to_shared(sCT) +
                            (((mm >> 1) * 8 + rr) * 36 + (mm & 1) * 4) * 4;
        const int ctaL = blockIdx.y * gridDim.x + blockIdx.x;
        uint4* gp = g_hpk + (size_t)ctaL * 1024;

#pragma unroll
        for (int jp = 0; jp < 4; jp++) {
            float az0[4] = {0.f, 0.f, 0.f, 0.f};
            float az1[4] = {0.f, 0.f, 0.f, 0.f};
#pragma unroll
            for (int kk = 0; kk < 4; kk++) {
                uint32_t a0, a1, a2, a3;
                ldm_x4(a0, a1, a2, a3, abase + kk * 32);
                uint32_t b0a, b1a, b0b, b1b;
                ldm_x4(b0a, b1a, b0b, b1b, cb + jp * 2304 + kk * 32);
                mma_f16(az0, a0, a1, a2, a3, b0a, b1a);
                mma_f16(az1, a0, a1, a2, a3, b0b, b1b);
            }
            uint4 Z;
            Z.x = pack_f16x2(az0[0], az0[1]);   // nt=2jp,   row r0
            Z.y = pack_f16x2(az0[2], az0[3]);   // nt=2jp,   row r1
            Z.z = pack_f16x2(az1[0], az1[1]);   // nt=2jp+1, row r0
            Z.w = pack_f16x2(az1[2], az1[3]);   // nt=2jp+1, row r1
            gp[jp * 256 + tid] = Z;
        }
    }

    // ---- MMA comm reduction: warp w contracts its own bb chunk [16w,16w+16)
    //      (coef stays fp16 hi/lo — comm is the precision-critical path)
    float dv[4][4];   // [jp][dA0,dA1,dB0,dB1]
    {
        uint32_t hb = (uint32_t)__cvta_generic_to_shared(sHp) +
                      (w * 16 + (mm & 1) * 8 + rr) * 144 + (mm >> 1) * 16;
        float2 cA = *(const float2*)(sC + g * 132 + 16 * w + 2 * t);
        float2 cB = *(const float2*)(sC + g * 132 + 16 * w + 8 + 2 * t);
        uint32_t a0l, a0h = split_pack_f16(cA.x, cA.y, a0l);
        uint32_t a2l, a2h = split_pack_f16(cB.x, cB.y, a2l);
#pragma unroll
        for (int jp = 0; jp < 4; jp++) {
            uint32_t b0a, b1a, b0b, b1b;
            ldm_x4_t(b0a, b1a, b0b, b1b, hb + jp * 32);
            float dA[4] = {0.f, 0.f, 0.f, 0.f};
            float dB[4] = {0.f, 0.f, 0.f, 0.f};
            mma_f16(dA, a0h, 0u, a2h, 0u, b0a, b1a);
            mma_f16(dA, a0l, 0u, a2l, 0u, b0a, b1a);
            mma_f16(dB, a0h, 0u, a2h, 0u, b0b, b1b);
            mma_f16(dB, a0l, 0u, a2l, 0u, b0b, b1b);
            dv[jp][0] = dA[0]; dv[jp][1] = dA[1];
            dv[jp][2] = dB[0]; dv[jp][3] = dB[1];
        }
    }
    __syncthreads();   // all reads of BIG (Wc plane + sHp) complete

    // stage per-warp partials into the dead BIG region: [w][i*65 + o]
    {
        float* sPart = sm + C_BIG;
#pragma unroll
        for (int jp = 0; jp < 4; jp++) {
            int oA = 16 * jp + 2 * t, oB = oA + 8;
            sPart[w * 520 + g * 65 + oA]     = dv[jp][0];
            sPart[w * 520 + g * 65 + oA + 1] = dv[jp][1];
            sPart[w * 520 + g * 65 + oB]     = dv[jp][2];
            sPart[w * 520 + g * 65 + oB + 1] = dv[jp][3];
        }
    }
    __syncthreads();

    // cross-warp sum: 512 outputs over 256 threads; atomic into replica
    {
        const float* sPart = sm + C_BIG;
        float* rep = g_commR[blockIdx.x & (NREP - 1)];
#pragma unroll
        for (int s = 0; s < 2; s++) {
            int idx = tid + s * 256;
            int i = idx >> 6, o = idx & 63;
            float sum = 0.f;
#pragma unroll
            for (int ww = 0; ww < 8; ww++)
                sum += sPart[ww * 520 + i * 65 + o];
            atomicAdd(&rep[idx], sum);
        }
    }
}

// pre2[n][o] = bc[n][o] + sum_h comm[n][h] * Wc[n][HX+h][o]
__global__ void k_pre(const float* __restrict__ Wc, const float* __restrict__ bc) {
    __shared__ float sComm[HXS];
    const int n = blockIdx.x, o = threadIdx.x;
    float cs = 0.f;
#pragma unroll 8
    for (int r = 0; r < NREP; r++)
        cs += g_commR[r][n * HXS + o];
    sComm[o] = cs;
    __syncthreads();
    float s = bc[n * HXS + o];
#pragma unroll 8
    for (int h = 0; h < HXS; h++)
        s = fmaf(sComm[h], Wc[n * 2 * HXS * HXS + (HXS + h) * HXS + o], s);
    g_pre2[n * HXS + o] = s;
}

// ---------------------------------------------------------------------------
// Kernel B: pure streaming epilogue — q = tanh(z + pre2) @ Wd + bd.
// ---------------------------------------------------------------------------
__global__ __launch_bounds__(256) void k_main(
    const float* __restrict__ Wd, const float* __restrict__ bd,
    float* __restrict__ out)
{
    __shared__ float sWd[HXS * ACTS];
    __shared__ float sP[HXS];
    __shared__ float sbd[8];

    const int tid = threadIdx.x;
    const int ctaL = NBLK * NAG - 1 - (blockIdx.y * gridDim.x + blockIdx.x);
    const int n    = ctaL / NBLK;
    const int b0   = (ctaL % NBLK) * TILE;

    for (int i = tid; i < HXS * ACTS; i += 256) sWd[i] = Wd[n * HXS * ACTS + i];
    if (tid < 64) sP[tid] = g_pre2[n * 64 + tid];
    if (tid < 5)  sbd[tid] = bd[n * 5 + tid];
    __syncthreads();

    const int lane = tid & 31, g = lane >> 2, t = lane & 3, w = tid >> 5;
    const int r0 = w * 16 + g, r1 = r0 + 8;
    const uint4* gp = g_hpk + (size_t)ctaL * 1024;

    float q0[ACTS], q1[ACTS];
#pragma unroll
    for (int a = 0; a < ACTS; a++) { q0[a] = 0.f; q1[a] = 0.f; }

#pragma unroll
    for (int jp = 0; jp < 4; jp++) {
        uint4 Z = gp[jp * 256 + tid];
#pragma unroll
        for (int s = 0; s < 2; s++) {
            int nt = 2 * jp + s;
            int c0 = nt * 8 + 2 * t;
            float p0 = sP[c0], p1 = sP[c0 + 1];
            uint32_t zr0 = s ? Z.z : Z.x;   // row r0: (c0, c0+1)
            uint32_t zr1 = s ? Z.w : Z.y;   // row r1
            float2 fa = __half22float2(*(const __half2*)&zr0);
            float2 fb = __half22float2(*(const __half2*)&zr1);
            float t00 = fast_tanh(fa.x + p0);
            float t01 = fast_tanh(fa.y + p1);
            float t10 = fast_tanh(fb.x + p0);
            float t11 = fast_tanh(fb.y + p1);
            const float* wd0 = sWd + c0 * 5;
            const float* wd1 = sWd + (c0 + 1) * 5;
#pragma unroll
            for (int a = 0; a < ACTS; a++) {
                q0[a] = fmaf(t00, wd0[a], fmaf(t01, wd1[a], q0[a]));
                q1[a] = fmaf(t10, wd0[a], fmaf(t11, wd1[a], q1[a]));
            }
        }
    }
#pragma unroll
    for (int a = 0; a < ACTS; a++) {
        q0[a] += __shfl_xor_sync(0xffffffffu, q0[a], 1);
        q0[a] += __shfl_xor_sync(0xffffffffu, q0[a], 2);
        q1[a] += __shfl_xor_sync(0xffffffffu, q1[a], 1);
        q1[a] += __shfl_xor_sync(0xffffffffu, q1[a], 2);
    }
    if (t == 0) {
        float* o0 = out + ((size_t)(b0 + r0) * NAG + n) * ACTS;
        float* o1 = out + ((size_t)(b0 + r1) * NAG + n) * ACTS;
#pragma unroll
        for (int a = 0; a < ACTS; a++) {
            o0[a] = q0[a] + sbd[a];
            o1[a] = q1[a] + sbd[a];
        }
    }
}

extern "C" void kernel_launch(void* const* d_in, const int* in_sizes, int n_in,
                              void* d_out, int out_size)
{
    const float* obs = (const float*)d_in[0];
    const float* W1  = (const float*)d_in[1];
    const float* b1  = (const float*)d_in[2];
    const float* W2  = (const float*)d_in[3];
    const float* b2  = (const float*)d_in[4];
    const float* Wc  = (const float*)d_in[5];
    const float* bc  = (const float*)d_in[6];
    const float* Wd  = (const float*)d_in[7];
    const float* bd  = (const float*)d_in[8];
    float* out = (float*)d_out;

    const int SMEM_C = C_TOT * sizeof(float);   // 49,024 B -> 4 CTAs/SM
    cudaFuncSetAttribute(k_comm, cudaFuncAttributeMaxDynamicSharedMemorySize, SMEM_C);

    k_zero<<<NREP, NAG * HXS>>>();
    k_comm<<<dim3(NBLK, NAG), 256, SMEM_C>>>(obs, W1, b1, W2, b2, Wc);
    k_pre<<<NAG, HXS>>>(Wc, bc);
    k_main<<<dim3(NBLK, NAG), 256>>>(Wd, bd, out);
}